// round 16
// baseline (speedup 1.0000x reference)
#include <cuda_runtime.h>
#include <cuda_bf16.h>
#include <stdint.h>
#include <math.h>

#define DIM 128
#define HEADS 4
#define NEG_SLOPE 0.2f
#define MAX_N 50000
#define MAX_E 600000
#define SCAN_CHUNK 1024
#define MAX_NB ((MAX_N + SCAN_CHUNK - 1) / SCAN_CHUNK)
#define WPREP_BLKS 256
#define SCAT_BLKS 1024

// ------------------- scratch (static device globals; no allocs) -------------------
__device__ float g_h[MAX_N * DIM];
__device__ float g_skip[MAX_N * DIM];
__device__ float g_buf1[MAX_N * DIM];
__device__ float g_asrc[MAX_N * HEADS];
__device__ float g_adst[MAX_N * HEADS];
__device__ int   g_deg[MAX_N];
__device__ int   g_off[MAX_N + 1];
__device__ int   g_cursor[MAX_N];
__device__ int   g_csr[MAX_E + MAX_N];
__device__ int   g_agg[MAX_NB];
__device__ int   g_flag[MAX_NB];
__device__ __nv_bfloat16 g_bhi[2 * 256 * 128];
__device__ __nv_bfloat16 g_blo[2 * 256 * 128];

// ------------------- prep (weights) + degree histogram, role-split -------------------
__global__ void prep_hist(const float* __restrict__ W1, const float* __restrict__ Ws1,
                          const float* __restrict__ W2, const float* __restrict__ Ws2,
                          const int* __restrict__ dst, int E) {
    int tid = threadIdx.x;
    if ((int)blockIdx.x < WPREP_BLKS) {
        int idx = blockIdx.x * 256 + tid;
        int layer = idx >> 15;
        int rem   = idx & 32767;
        int n     = rem >> 7;
        int k     = rem & 127;
        const float* W = layer ? (n < 128 ? W2 : Ws2) : (n < 128 ? W1 : Ws1);
        float v = W[k * 128 + (n & 127)];
        __nv_bfloat16 hi = __float2bfloat16(v);
        float lo = v - __bfloat162float(hi);
        g_bhi[idx] = hi;
        g_blo[idx] = __float2bfloat16(lo);
    } else {
        int nbh = gridDim.x - WPREP_BLKS;
        for (int i = (blockIdx.x - WPREP_BLKS) * 256 + tid; i < E; i += nbh * 256)
            atomicAdd(&g_deg[dst[i]], 1);
    }
}

// ------------------- single-kernel scan with decoupled lookback -------------------
__global__ void scan_lookback(int N) {
    __shared__ int wsum[8];
    __shared__ int s_base;
    int tid = threadIdx.x;
    int lane = tid & 31, warp = tid >> 5;
    int b = blockIdx.x;
    int i0 = b * SCAN_CHUNK + tid * 4;

    int4 d = make_int4(0, 0, 0, 0);
    if (i0 + 3 < N) {
        d = *(const int4*)(g_deg + i0);
        *(int4*)(g_deg + i0) = make_int4(0, 0, 0, 0);
        d.x += 1; d.y += 1; d.z += 1; d.w += 1;
    } else {
        if (i0 + 0 < N) { d.x = g_deg[i0 + 0] + 1; g_deg[i0 + 0] = 0; }
        if (i0 + 1 < N) { d.y = g_deg[i0 + 1] + 1; g_deg[i0 + 1] = 0; }
        if (i0 + 2 < N) { d.z = g_deg[i0 + 2] + 1; g_deg[i0 + 2] = 0; }
        if (i0 + 3 < N) { d.w = g_deg[i0 + 3] + 1; g_deg[i0 + 3] = 0; }
    }
    int T = d.x + d.y + d.z + d.w;
    int v = T;
    #pragma unroll
    for (int o = 1; o < 32; o <<= 1) {
        int t = __shfl_up_sync(0xffffffffu, v, o);
        if (lane >= o) v += t;
    }
    if (lane == 31) wsum[warp] = v;
    __syncthreads();
    if (warp == 0) {
        int w = (lane < 8) ? wsum[lane] : 0;
        #pragma unroll
        for (int o = 1; o < 8; o <<= 1) {
            int t = __shfl_up_sync(0xffffffffu, w, o);
            if (lane >= o) w += t;
        }
        if (lane < 8) wsum[lane] = w;
        if (lane == 0) {
            g_agg[b] = wsum[7];
            __threadfence();
            atomicExch(&g_flag[b], 1);
        }
    }
    __syncthreads();
    int blk_scan = (warp ? wsum[warp - 1] : 0);

    if (warp == 0) {
        int base = 0;
        for (int i = lane; i < b; i += 32) {
            while (atomicAdd(&g_flag[i], 0) == 0) {}
            base += g_agg[i];
        }
        #pragma unroll
        for (int o = 16; o > 0; o >>= 1) base += __shfl_xor_sync(0xffffffffu, base, o);
        if (lane == 0) s_base = base;
    }
    __syncthreads();

    int excl = v - T + blk_scan + s_base;
    int p = excl;
    if (i0 + 0 < N) { g_cursor[i0 + 0] = p; g_off[i0 + 1] = p + d.x; p += d.x; }
    if (i0 + 1 < N) { g_cursor[i0 + 1] = p; g_off[i0 + 2] = p + d.y; p += d.y; }
    if (i0 + 2 < N) { g_cursor[i0 + 2] = p; g_off[i0 + 3] = p + d.z; p += d.z; }
    if (i0 + 3 < N) { g_cursor[i0 + 3] = p; g_off[i0 + 4] = p + d.w; }
    if (b == 0 && tid == 0) g_off[0] = 0;
}

// ------------------- MMA / ldmatrix helpers -------------------
__device__ __forceinline__ void mma_bf16(float c[4], const uint32_t a[4],
                                         uint32_t b0, uint32_t b1) {
    asm volatile(
        "mma.sync.aligned.m16n8k16.row.col.f32.bf16.bf16.f32 "
        "{%0,%1,%2,%3}, {%4,%5,%6,%7}, {%8,%9}, {%0,%1,%2,%3};"
        : "+f"(c[0]), "+f"(c[1]), "+f"(c[2]), "+f"(c[3])
        : "r"(a[0]), "r"(a[1]), "r"(a[2]), "r"(a[3]), "r"(b0), "r"(b1));
}
__device__ __forceinline__ void ldsm_x4(uint32_t d[4], uint32_t addr) {
    asm volatile("ldmatrix.sync.aligned.m8n8.x4.shared.b16 {%0,%1,%2,%3}, [%4];"
                 : "=r"(d[0]), "=r"(d[1]), "=r"(d[2]), "=r"(d[3]) : "r"(addr));
}
__device__ __forceinline__ uint32_t s2u(const void* p) {
    return (uint32_t)__cvta_generic_to_shared(p);
}
__device__ __forceinline__ uint32_t pack_bf16hi(float a, float b) {
    return ((uint32_t)__bfloat16_as_ushort(__float2bfloat16(b)) << 16)
         | __bfloat16_as_ushort(__float2bfloat16(a));
}

// ------------------- fused HMMA GEMM, tile 64x128, 3 CTAs/SM [+ scatter side-blocks] --
// GEMM blocks: bm = blockIdx.x >> 1 (64-row tile), bn = blockIdx.x & 1 (128-col half).
// bn==0 -> g_h + attention logits (head = wn); bn==1 -> g_skip.
// smem (u32 words): Ah[64*68] Al[64*68] Bh[128*36] Bl[128*36] = 17920 words.
__global__ void __launch_bounds__(256, 3)
gat_mma_fused(const float* __restrict__ X,
              const uint32_t* __restrict__ Bhi, const uint32_t* __restrict__ Blo,
              const float* __restrict__ a_src, const float* __restrict__ a_dst,
              int nrows, int gemm_nb,
              const int* __restrict__ srcE, const int* __restrict__ dstE, int E) {
    int tid = threadIdx.x;

    if ((int)blockIdx.x >= gemm_nb) {   // ---- scatter role ----
        int nbs = gridDim.x - gemm_nb;
        int base = (blockIdx.x - gemm_nb) * 256 + tid;
        if (base < MAX_NB) g_flag[base] = 0;
        for (int i = base; i < E + nrows; i += nbs * 256) {
            int s, dn;
            if (i < E) { s = srcE[i]; dn = dstE[i]; }
            else       { s = dn = i - E; }
            int p = atomicAdd(&g_cursor[dn], 1);
            g_csr[p] = s;
        }
        return;
    }

    extern __shared__ uint32_t dsm[];
    __shared__ float s_att[256];
    uint32_t* Ah = dsm;             // 64*68 = 4352
    uint32_t* Al = dsm + 4352;
    uint32_t* Bh = dsm + 8704;      // 128*36 = 4608
    uint32_t* Bl = dsm + 13312;

    int bm = blockIdx.x >> 1;
    int bn = blockIdx.x & 1;
    int row0 = bm * 64;
    if (tid < 128) { s_att[tid] = a_src[tid]; s_att[128 + tid] = a_dst[tid]; }

    // A staging: 2048 float4 loads across 256 thr = 8 iters
    #pragma unroll
    for (int it = 0; it < 8; it++) {
        int idx = tid + it * 256;
        int r = idx >> 5;
        int c4 = idx & 31;
        float4 xv = make_float4(0.f, 0.f, 0.f, 0.f);
        int gr = row0 + r;
        if (gr < nrows)
            xv = *(const float4*)(X + (size_t)gr * 128 + c4 * 4);
        uint32_t h0 = pack_bf16hi(xv.x, xv.y);
        uint32_t h1 = pack_bf16hi(xv.z, xv.w);
        float lx = xv.x - __bfloat162float(__float2bfloat16(xv.x));
        float ly = xv.y - __bfloat162float(__float2bfloat16(xv.y));
        float lz = xv.z - __bfloat162float(__float2bfloat16(xv.z));
        float lw = xv.w - __bfloat162float(__float2bfloat16(xv.w));
        uint32_t l0 = pack_bf16hi(lx, ly);
        uint32_t l1 = pack_bf16hi(lz, lw);
        int w = c4 * 2;
        *(uint2*)(Ah + r * 68 + w) = make_uint2(h0, h1);
        *(uint2*)(Al + r * 68 + w) = make_uint2(l0, l1);
    }

    int lane = tid & 31, warp = tid >> 5;
    int wm = warp & 1, wn = warp >> 1;     // wm: 32-row half, wn: 32-col quarter
    int g = lane >> 2, t = lane & 3;
    int mloc  = wm * 32;
    int nloc  = wn * 32;

    uint32_t a_off = (uint32_t)(((mloc + (lane & 15)) * 68 + ((lane >> 4) << 2)) * 4);
    uint32_t ah_base = s2u(Ah) + a_off;
    uint32_t al_base = s2u(Al) + a_off;
    uint32_t b_off = (uint32_t)((((nloc + ((lane >> 4) << 3) + (lane & 7)) * 36)
                                 + (((lane >> 3) & 1) << 2)) * 4);
    uint32_t bh_base = s2u(Bh) + b_off;
    uint32_t bl_base = s2u(Bl) + b_off;

    float acc[2][4][4];
    #pragma unroll
    for (int a = 0; a < 2; a++)
        #pragma unroll
        for (int b = 0; b < 4; b++)
            #pragma unroll
            for (int c = 0; c < 4; c++) acc[a][b][c] = 0.f;

    const uint32_t* BhiG = Bhi + (size_t)bn * 128 * 64;
    const uint32_t* BloG = Blo + (size_t)bn * 128 * 64;

    for (int kc = 0; kc < 2; kc++) {
        if (kc) __syncthreads();
        // B staging: 128 rows x 16 uint2 = 2048 uint2 across 256 thr = 8 iters
        #pragma unroll
        for (int it = 0; it < 8; it++) {
            int idx = tid + it * 256;      // 0..2047
            int r = idx >> 4;
            int w = (idx & 15) * 2;
            *(uint2*)(Bh + r * 36 + w) = *(const uint2*)(BhiG + r * 64 + kc * 32 + w);
            *(uint2*)(Bl + r * 36 + w) = *(const uint2*)(BloG + r * 64 + kc * 32 + w);
        }
        __syncthreads();

        #pragma unroll
        for (int ksl = 0; ksl < 4; ksl++) {
            uint32_t kb = (uint32_t)((kc * 32 + ksl * 8) * 4);
            uint32_t bb = (uint32_t)((ksl * 8) * 4);
            uint32_t ah[2][4], al[2][4], bf[2][4];
            ldsm_x4(ah[0], ah_base + kb);
            ldsm_x4(ah[1], ah_base + kb + 16 * 68 * 4);
            ldsm_x4(al[0], al_base + kb);
            ldsm_x4(al[1], al_base + kb + 16 * 68 * 4);
            #pragma unroll
            for (int q = 0; q < 2; q++)
                ldsm_x4(bf[q], bh_base + bb + (uint32_t)(q * 16 * 36 * 4));
            #pragma unroll
            for (int q = 0; q < 2; q++) {
                mma_bf16(acc[0][2 * q],     ah[0], bf[q][0], bf[q][1]);
                mma_bf16(acc[1][2 * q],     ah[1], bf[q][0], bf[q][1]);
                mma_bf16(acc[0][2 * q + 1], ah[0], bf[q][2], bf[q][3]);
                mma_bf16(acc[1][2 * q + 1], ah[1], bf[q][2], bf[q][3]);
            }
            #pragma unroll
            for (int q = 0; q < 2; q++) {
                mma_bf16(acc[0][2 * q],     al[0], bf[q][0], bf[q][1]);
                mma_bf16(acc[1][2 * q],     al[1], bf[q][0], bf[q][1]);
                mma_bf16(acc[0][2 * q + 1], al[0], bf[q][2], bf[q][3]);
                mma_bf16(acc[1][2 * q + 1], al[1], bf[q][2], bf[q][3]);
            }
            #pragma unroll
            for (int q = 0; q < 2; q++)
                ldsm_x4(bf[q], bl_base + bb + (uint32_t)(q * 16 * 36 * 4));
            #pragma unroll
            for (int q = 0; q < 2; q++) {
                mma_bf16(acc[0][2 * q],     ah[0], bf[q][0], bf[q][1]);
                mma_bf16(acc[1][2 * q],     ah[1], bf[q][0], bf[q][1]);
                mma_bf16(acc[0][2 * q + 1], ah[0], bf[q][2], bf[q][3]);
                mma_bf16(acc[1][2 * q + 1], ah[1], bf[q][2], bf[q][3]);
            }
        }
    }

    int gr0 = row0 + mloc;
    if (bn == 0) {
        // columns nloc + nt*8 + t*2 all within head wn
        float ps[2][2] = {{0.f, 0.f}, {0.f, 0.f}};
        float pd[2][2] = {{0.f, 0.f}, {0.f, 0.f}};
        #pragma unroll
        for (int mt = 0; mt < 2; mt++) {
            int r0 = gr0 + mt * 16 + g;
            int r1 = r0 + 8;
            #pragma unroll
            for (int nt = 0; nt < 4; nt++) {
                int col = nloc + nt * 8 + t * 2;
                float s0 = s_att[col],       s1 = s_att[col + 1];
                float d0 = s_att[128 + col], d1 = s_att[128 + col + 1];
                ps[mt][0] += acc[mt][nt][0] * s0 + acc[mt][nt][1] * s1;
                pd[mt][0] += acc[mt][nt][0] * d0 + acc[mt][nt][1] * d1;
                ps[mt][1] += acc[mt][nt][2] * s0 + acc[mt][nt][3] * s1;
                pd[mt][1] += acc[mt][nt][2] * d0 + acc[mt][nt][3] * d1;
                if (r0 < nrows)
                    *(float2*)(g_h + (size_t)r0 * 128 + col) =
                        make_float2(acc[mt][nt][0], acc[mt][nt][1]);
                if (r1 < nrows)
                    *(float2*)(g_h + (size_t)r1 * 128 + col) =
                        make_float2(acc[mt][nt][2], acc[mt][nt][3]);
            }
        }
        #pragma unroll
        for (int mt = 0; mt < 2; mt++)
            #pragma unroll
            for (int rs = 0; rs < 2; rs++) {
                float vs = ps[mt][rs];
                float vd = pd[mt][rs];
                vs += __shfl_xor_sync(0xffffffffu, vs, 1);
                vs += __shfl_xor_sync(0xffffffffu, vs, 2);
                vd += __shfl_xor_sync(0xffffffffu, vd, 1);
                vd += __shfl_xor_sync(0xffffffffu, vd, 2);
                if (t == 0) {
                    int r = gr0 + mt * 16 + g + rs * 8;
                    if (r < nrows) {
                        g_asrc[r * 4 + wn] = vs;
                        g_adst[r * 4 + wn] = vd;
                    }
                }
            }
    } else {
        #pragma unroll
        for (int mt = 0; mt < 2; mt++) {
            int r0 = gr0 + mt * 16 + g;
            int r1 = r0 + 8;
            #pragma unroll
            for (int nt = 0; nt < 4; nt++) {
                int col = nloc + nt * 8 + t * 2;
                if (r0 < nrows)
                    *(float2*)(g_skip + (size_t)r0 * 128 + col) =
                        make_float2(acc[mt][nt][0], acc[mt][nt][1]);
                if (r1 < nrows)
                    *(float2*)(g_skip + (size_t)r1 * 128 + col) =
                        make_float2(acc[mt][nt][2], acc[mt][nt][3]);
            }
        }
    }
}

// ------------------- softmax aggregate: exact CSR, no-max exp, 4-edge batched --------
__global__ void __launch_bounds__(256)
agg_kernel(const float* __restrict__ bias, float* __restrict__ out, int N) {
    int gw = (blockIdx.x * blockDim.x + threadIdx.x) >> 5;
    int lane = threadIdx.x & 31;
    if (gw >= N) return;
    int n = gw;
    int beg = g_off[n];
    int end = g_off[n + 1];
    int head = lane >> 3;

    float adh = g_adst[n * 4 + head];
    const float4* h4 = (const float4*)g_h;

    float denom = 0.0f;
    float4 acc = make_float4(0.f, 0.f, 0.f, 0.f);

    int j = beg;
    for (; j + 4 <= end; j += 4) {
        int s0 = g_csr[j];
        int s1 = g_csr[j + 1];
        int s2 = g_csr[j + 2];
        int s3 = g_csr[j + 3];
        float a0 = g_asrc[s0 * 4 + head];
        float a1 = g_asrc[s1 * 4 + head];
        float a2 = g_asrc[s2 * 4 + head];
        float a3 = g_asrc[s3 * 4 + head];
        float4 v0 = h4[s0 * 32 + lane];
        float4 v1 = h4[s1 * 32 + lane];
        float4 v2 = h4[s2 * 32 + lane];
        float4 v3 = h4[s3 * 32 + lane];

        float e0 = a0 + adh; e0 = fmaxf(e0, NEG_SLOPE * e0);
        float e1 = a1 + adh; e1 = fmaxf(e1, NEG_SLOPE * e1);
        float e2 = a2 + adh; e2 = fmaxf(e2, NEG_SLOPE * e2);
        float e3 = a3 + adh; e3 = fmaxf(e3, NEG_SLOPE * e3);

        float w0 = __expf(e0);
        float w1 = __expf(e1);
        float w2 = __expf(e2);
        float w3 = __expf(e3);
        denom += (w0 + w1) + (w2 + w3);
        acc.x += w0 * v0.x + w1 * v1.x + w2 * v2.x + w3 * v3.x;
        acc.y += w0 * v0.y + w1 * v1.y + w2 * v2.y + w3 * v3.y;
        acc.z += w0 * v0.z + w1 * v1.z + w2 * v2.z + w3 * v3.z;
        acc.w += w0 * v0.w + w1 * v1.w + w2 * v2.w + w3 * v3.w;
    }
    for (; j < end; j++) {
        int s = g_csr[j];
        float a = g_asrc[s * 4 + head];
        float e = a + adh; e = fmaxf(e, NEG_SLOPE * e);
        float4 v = h4[s * 32 + lane];
        float w = __expf(e);
        denom += w;
        acc.x += w * v.x; acc.y += w * v.y; acc.z += w * v.z; acc.w += w * v.w;
    }

    float inv = 1.0f / (denom + 1e-16f);
    float4 b  = ((const float4*)bias)[lane];
    float4 sk = ((const float4*)g_skip)[(size_t)n * 32 + lane];
    float4 o;
    o.x = acc.x * inv + b.x + sk.x;
    o.y = acc.y * inv + b.y + sk.y;
    o.z = acc.z * inv + b.z + sk.z;
    o.w = acc.w * inv + b.w + sk.w;
    o.x = (o.x > 0.f) ? o.x : expm1f(o.x);
    o.y = (o.y > 0.f) ? o.y : expm1f(o.y);
    o.z = (o.z > 0.f) ? o.z : expm1f(o.z);
    o.w = (o.w > 0.f) ? o.w : expm1f(o.w);
    ((float4*)out)[(size_t)n * 32 + lane] = o;
}

// ------------------- launch -------------------
extern "C" void kernel_launch(void* const* d_in, const int* in_sizes, int n_in,
                              void* d_out, int out_size) {
    const float* x    = (const float*)d_in[0];
    const int*   ei   = (const int*)  d_in[1];
    const float* W1   = (const float*)d_in[2];
    const float* as1  = (const float*)d_in[3];
    const float* ad1  = (const float*)d_in[4];
    const float* b1   = (const float*)d_in[5];
    const float* Ws1  = (const float*)d_in[6];
    const float* W2   = (const float*)d_in[7];
    const float* as2  = (const float*)d_in[8];
    const float* ad2  = (const float*)d_in[9];
    const float* b2   = (const float*)d_in[10];
    const float* Ws2  = (const float*)d_in[11];

    int N = in_sizes[0] / DIM;
    int E = in_sizes[1] / 2;
    const int* src = ei;
    const int* dst = ei + E;

    float* buf1;  cudaGetSymbolAddress((void**)&buf1, g_buf1);
    __nv_bfloat16* bhi; cudaGetSymbolAddress((void**)&bhi, g_bhi);
    __nv_bfloat16* blo; cudaGetSymbolAddress((void**)&blo, g_blo);

    const size_t dyn = 17920 * 4;   // 71680 B
    cudaFuncSetAttribute(gat_mma_fused, cudaFuncAttributeMaxDynamicSharedMemorySize, (int)dyn);

    int nb = (N + SCAN_CHUNK - 1) / SCAN_CHUNK;
    int gemm_blocks = 2 * ((N + 63) / 64);   // x2: N-halves
    int warp_blocks = (N * 32 + 255) / 256;

    prep_hist<<<WPREP_BLKS + 1024, 256>>>(W1, Ws1, W2, Ws2, dst, E);         // 0
    scan_lookback<<<nb, 256>>>(N);                                           // 1
    gat_mma_fused<<<gemm_blocks + SCAT_BLKS, 256, dyn>>>(                    // 2 (gemm1+scatter)
        x, (const uint32_t*)bhi, (const uint32_t*)blo, as1, ad1, N,
        gemm_blocks, src, dst, E);
    agg_kernel<<<warp_blocks, 256>>>(b1, buf1, N);                           // 3 <- profiled
    gat_mma_fused<<<gemm_blocks, 256, dyn>>>(                                // 4 (gemm2)
        buf1, (const uint32_t*)(bhi + 256 * 128), (const uint32_t*)(blo + 256 * 128),
        as2, ad2, N, gemm_blocks, nullptr, nullptr, 0);
    agg_kernel<<<warp_blocks, 256>>>(b2, (float*)d_out, N);                  // 5
}